// round 9
// baseline (speedup 1.0000x reference)
#include <cuda_runtime.h>
#include <cstdint>

// ---------------------------------------------------------------------------
// TreeCnnLayer: y[b,l,o] = relu( sum_{k=0..3} sum_i x[b, idx[l,k], i] * mask[k,i,o] + bias[127] )
// Gathered GEMM: M=131072, K=512, N=128.  mma.sync tf32 (plain sm_100 target).
// R9: B (weights) removed from smem entirely. Prep builds a fragment-native
//     B image (per k-step/col-block, lane-indexed float2) read via coalesced
//     LDG.64 straight into mma fragments. A stays in smem (gather), 3-stage
//     cp.async ring, one barrier per chunk. Crossbar bytes/chunk: 128K -> 48K.
// ---------------------------------------------------------------------------

#define BATCH   16
#define NROWS   8192
#define TILE_M  128
#define NTILES  (NROWS / TILE_M)    // 64
#define BK      32
#define NCHUNK  16                  // 512 / 32
#define ASTR    36                  // A smem row stride (floats)

#define A_STAGE_B  18432            // 128 rows * 144 B
#define SIDX_B     2048
#define NSTAGE     3
#define SMEM_TOTAL (SIDX_B + NSTAGE * A_STAGE_B)   // 57344

// Fragment-native B image: for k-step s (0..63), col-block nf (0..15), lane
// (0..31): float2 = (bb0, bb1) = W^T values at (o = nf*8 + lane/4,
// i = s*8 + lane%4 + {0,4}).  Warp load of one (s,nf) = 256 contiguous bytes.
__device__ float g_Bfrag[64 * 16 * 32 * 2];

__device__ __forceinline__ uint32_t smem_u32(const void* p) {
    uint32_t a;
    asm("{ .reg .u64 t; cvta.to.shared.u64 t, %1; cvt.u32.u64 %0, t; }" : "=r"(a) : "l"(p));
    return a;
}
__device__ __forceinline__ uint32_t f2tf32(float f) {
    uint32_t u;
    asm("cvt.rna.tf32.f32 %0, %1;" : "=r"(u) : "f"(f));
    return u;
}
__device__ __forceinline__ void cp_async16_cg(uint32_t dst, const void* src) {
    asm volatile("cp.async.cg.shared.global [%0], [%1], 16;" :: "r"(dst), "l"(src));
}
__device__ __forceinline__ void mma_tf32(float* d, const uint32_t* a, const uint32_t* b) {
    asm volatile(
        "mma.sync.aligned.m16n8k8.row.col.f32.tf32.tf32.f32 "
        "{%0,%1,%2,%3}, {%4,%5,%6,%7}, {%8,%9}, {%0,%1,%2,%3};"
        : "+f"(d[0]), "+f"(d[1]), "+f"(d[2]), "+f"(d[3])
        : "r"(a[0]), "r"(a[1]), "r"(a[2]), "r"(a[3]), "r"(b[0]), "r"(b[1]));
}

// ---------------- prep: build fragment-native tf32 B image ----------------
__global__ void prep_w_kernel(const float* __restrict__ mask) {
    int t = blockIdx.x * blockDim.x + threadIdx.x;   // 0..65535
    int j    = t & 1;
    int lane = (t >> 1) & 31;
    int nf   = (t >> 6) & 15;
    int s    = t >> 10;                              // k-step 0..63
    int qc = lane & 3, gr = lane >> 2;
    int o  = nf * 8 + gr;
    int ig = s * 8 + qc + 4 * j;                     // global k index 0..511
    int k  = ig >> 7, i = ig & 127;
    g_Bfrag[t] = __uint_as_float(f2tf32(mask[(k << 14) + (i << 7) + o]));
}

// ---------------- main kernel ----------------
__global__ void __launch_bounds__(256, 2)
tree_gemm(const float* __restrict__ x, const float* __restrict__ bias,
          const int* __restrict__ itab32, float* __restrict__ out)
{
    extern __shared__ char smem[];
    int* sIdx = (int*)smem;
    const uint32_t sbase = smem_u32(smem);

    const int tid  = threadIdx.x;
    const int lane = tid & 31;
    const int wid  = tid >> 5;          // 8 warps: 4M x 2N
    const int wm   = wid >> 1;          // 0..3
    const int wn   = wid & 1;           // 0..1
    const int gr   = lane >> 2;
    const int qc   = lane & 3;
    const int b    = blockIdx.y;
    const int V    = blockIdx.x * TILE_M;

    // index dtype autodetect (int64 LE: word[1]=hi(tab[0,0])=0; int32: tab[0,1]=8191)
    const int istride = (itab32[1] == 0) ? 2 : 1;
    const float bv = bias[127];

    #pragma unroll
    for (int j = tid; j < 512; j += 256) {
        int k = j >> 7, r = j & 127;
        sIdx[j] = itab32[(size_t)(((V + r) << 2) + k) * istride];
    }
    __syncthreads();

    const char* xb = (const char*)(x + (size_t)b * NROWS * 128);

    // Per-warp B fragment pointer: (s, nf=wn*8, lane) -> float2
    const float2* Bf = (const float2*)g_Bfrag + (size_t)(wn * 8) * 32 + lane;

    // A stage byte offsets, rotated through registers.
    uint32_t aCur = SIDX_B;
    uint32_t aNxt = SIDX_B + A_STAGE_B;
    uint32_t aPre = SIDX_B + 2 * A_STAGE_B;

    auto load_chunk = [&](int c, uint32_t aOff) {
        const int k  = c >> 2;
        const int c0 = (c & 3) * BK;
        const uint32_t aB = sbase + aOff;
        // A: 128 rows x 32 floats, 16B segs; seg = r*8 + cs
        #pragma unroll
        for (int i = 0; i < 4; i++) {
            int seg = tid + i * 256;
            int r = seg >> 3, cs = seg & 7;
            int g = sIdx[(k << 7) + r];
            cp_async16_cg(aB + r * 144 + cs * 16,
                          xb + (((size_t)g << 7) + c0 + (cs << 2)) * 4);
        }
        asm volatile("cp.async.commit_group;");
    };

    float acc[2][8][4];
    #pragma unroll
    for (int mf = 0; mf < 2; mf++)
        #pragma unroll
        for (int nf = 0; nf < 8; nf++)
            #pragma unroll
            for (int q = 0; q < 4; q++) acc[mf][nf][q] = 0.0f;

    load_chunk(0, aCur);
    load_chunk(1, aNxt);

    for (int c = 0; c < NCHUNK; c++) {
        if (c < NCHUNK - 1) asm volatile("cp.async.wait_group 1;");
        else                asm volatile("cp.async.wait_group 0;");
        __syncthreads();

        if (c + 2 < NCHUNK) load_chunk(c + 2, aPre);

        const float* A = (const float*)(smem + aCur);

        #pragma unroll
        for (int ks = 0; ks < 4; ks++) {
            const int kc = ks << 3;
            // B fragments straight from GMEM (L1/L2-resident, coalesced 256B/warp)
            const float2* bfp = Bf + (size_t)((c << 2) + ks) * (16 * 32);
            uint32_t bb[8][2];
            #pragma unroll
            for (int nf = 0; nf < 8; nf++) {
                float2 v = __ldg(bfp + nf * 32);
                bb[nf][0] = __float_as_uint(v.x);
                bb[nf][1] = __float_as_uint(v.y);
            }
            // A fragments (warp rows wm*32 .. +31): LDS + cvt.rna
            uint32_t a[2][4];
            #pragma unroll
            for (int mf = 0; mf < 2; mf++) {
                const float* ap = A + (wm * 32 + mf * 16 + gr) * ASTR + kc + qc;
                a[mf][0] = f2tf32(ap[0]);
                a[mf][1] = f2tf32(ap[8 * ASTR]);
                a[mf][2] = f2tf32(ap[4]);
                a[mf][3] = f2tf32(ap[8 * ASTR + 4]);
            }
            #pragma unroll
            for (int mf = 0; mf < 2; mf++)
                #pragma unroll
                for (int nf = 0; nf < 8; nf++)
                    mma_tf32(acc[mf][nf], a[mf], bb[nf]);
        }

        uint32_t t = aCur; aCur = aNxt; aNxt = aPre; aPre = t;
    }

    // ---- epilogue: +bias[127], relu, store ----
    float* ob = out + ((size_t)b * NROWS + V + wm * 32) * 128 + wn * 64;

    #pragma unroll
    for (int mf = 0; mf < 2; mf++) {
        #pragma unroll
        for (int nf = 0; nf < 8; nf++) {
            int row = mf * 16 + gr;
            int col = nf * 8 + 2 * qc;
            float2 v0, v1;
            v0.x = fmaxf(acc[mf][nf][0] + bv, 0.0f);
            v0.y = fmaxf(acc[mf][nf][1] + bv, 0.0f);
            v1.x = fmaxf(acc[mf][nf][2] + bv, 0.0f);
            v1.y = fmaxf(acc[mf][nf][3] + bv, 0.0f);
            *(float2*)(ob + (size_t)row * 128 + col)       = v0;
            *(float2*)(ob + (size_t)(row + 8) * 128 + col) = v1;
        }
    }
}

// ---------------- launch ----------------
extern "C" void kernel_launch(void* const* d_in, const int* in_sizes, int n_in,
                              void* d_out, int out_size)
{
    const float* x = nullptr;
    const float* mask = nullptr;
    const float* bias = nullptr;
    const int*   itab = nullptr;
    for (int i = 0; i < n_in; i++) {
        switch (in_sizes[i]) {
            case 16777216: x    = (const float*)d_in[i]; break;
            case 65536:    mask = (const float*)d_in[i]; break;
            case 128:      bias = (const float*)d_in[i]; break;
            case 32768:    itab = (const int*)d_in[i];   break;
            default: break;
        }
    }
    float* out = (float*)d_out;

    cudaFuncSetAttribute(tree_gemm,
                         cudaFuncAttributeMaxDynamicSharedMemorySize, SMEM_TOTAL);

    prep_w_kernel<<<256, 256>>>(mask);

    dim3 grid(NTILES, BATCH);
    tree_gemm<<<grid, 256, SMEM_TOTAL>>>(x, bias, itab, out);
}